// round 6
// baseline (speedup 1.0000x reference)
#include <cuda_runtime.h>
#include <math_constants.h>

#define WSZ    8
#define P2     64
#define CH     128
#define W1G    32
#define NWPB   1024
#define BATCH  8
#define NWIN   (BATCH*NWPB)
#define HD     32
#define NH     4
#define SHIFT  4
#define STR    132          // [tok][ch] padded row stride (floats)
#define PSTR   33           // [ch][pair] row stride in u64 (32 pairs + pad)
#define NTHR   512

typedef unsigned long long u64;

__device__ __forceinline__ u64 pack2(float lo, float hi) {
    u64 r; asm("mov.b64 %0, {%1, %2};" : "=l"(r) : "f"(lo), "f"(hi)); return r;
}
__device__ __forceinline__ void unpack2(u64 v, float& lo, float& hi) {
    asm("mov.b64 {%0, %1}, %2;" : "=f"(lo), "=f"(hi) : "l"(v));
}
__device__ __forceinline__ void ffma2(u64& d, u64 a, u64 b) {
    asm("fma.rn.f32x2 %0, %1, %2, %0;" : "+l"(d) : "l"(a), "l"(b));
}

// ---------------- scratch ----------------
__device__ float g_xw [(size_t)NWIN * P2 * CH];          // [win][tok][ch]
__device__ u64   g_xwT[(size_t)NWIN * CH * (P2/2)];      // [win][ch][pair]
__device__ float g_off[NWIN * P2 * 2];
__device__ float g_oi [NWIN * 2];

// ---------------- kernel 1: window gather + offset MLPs + transpose ----------------
__global__ __launch_bounds__(256)
void k_prep(const float* __restrict__ x,
            const float* __restrict__ wi_w, const float* __restrict__ wi_b,
            const float* __restrict__ w1_w, const float* __restrict__ w1_b,
            const float* __restrict__ w2_w, const float* __restrict__ w2_b)
{
    __shared__ float sT[P2 * STR];
    __shared__ float sT1[P2 * 2];

    const int win = blockIdx.x;
    const int b   = win >> 10;
    const int wr  = win & 1023;
    const int wi  = wr >> 5;
    const int wj  = wr & 31;
    const int tid = threadIdx.x;

    float4* gx4 = (float4*)(g_xw + (size_t)win * P2 * CH);

    for (int i4 = tid; i4 < P2 * CH / 4; i4 += 256) {
        const int tok = i4 >> 5, c4 = i4 & 31;
        const int pi = tok >> 3, pj = tok & 7;
        const int r = (wi * 8 + pi + SHIFT) & 255;
        const int c = (wj * 8 + pj + SHIFT) & 255;
        const float4 v = *(const float4*)(x + (size_t)((((b << 8) + r) << 8) + c) * CH + c4 * 4);
        *(float4*)(sT + tok * STR + c4 * 4) = v;
        gx4[i4] = v;
    }
    __syncthreads();

    // transposed pair copy: g_xwT[win][ch][pair]
    {
        u64* dst = g_xwT + (size_t)win * CH * 32;
        for (int i = tid; i < CH * 32; i += 256) {
            const int pr = i & 31, ch = i >> 5;
            dst[ch * 32 + pr] = pack2(sT[(2 * pr) * STR + ch], sT[(2 * pr + 1) * STR + ch]);
        }
    }

    {
        const int kind = tid >> 7;
        const int rem  = tid & 127;
        const int tok  = rem >> 1;
        const int d    = rem & 1;
        const float* w = kind ? w1_w : wi_w;
        float acc = 0.f;
        #pragma unroll 8
        for (int ch = 0; ch < 128; ++ch)
            acc = fmaf(sT[tok * STR + ch], w[ch * 2 + d], acc);
        if (kind) sT1[tok * 2 + d] = acc + w1_b[d];
        else      g_off[win * 128 + tok * 2 + d] = acc + wi_b[d];
    }
    __syncthreads();

    if (tid < 2) {
        float acc = w2_b[tid];
        for (int f = 0; f < 128; ++f)
            acc = fmaf(sT1[f], w2_w[f * 2 + tid], acc);
        g_oi[win * 2 + tid] = acc;
    }
}

// 64x128 GEMM on token-pairs via FFMA2. 8 active warps: warp g owns tokens
// g*8..g*8+7 (pairs 4g..4g+3); lane tx owns cols 4tx..4tx+3.
// Per ci: 1 LDG.128 (W) + 4 LDS.64 bc (A pairs) + 4 packs + 16 FFMA2.
__device__ __forceinline__
void gemm_p(const u64* __restrict__ inP, const float* __restrict__ w,
            int wstride, int woff, const float* __restrict__ bias, int boff,
            float* __restrict__ out_s, int g, int tx)
{
    u64 acc[4][4] = {};
    const float* wbase = w + woff + tx * 4;
    const u64*   ap0   = inP + 4 * g;
    #pragma unroll 4
    for (int ci = 0; ci < 128; ++ci) {
        const float4 wv = __ldg((const float4*)(wbase + (size_t)ci * wstride));
        const u64 w0 = pack2(wv.x, wv.x), w1 = pack2(wv.y, wv.y);
        const u64 w2 = pack2(wv.z, wv.z), w3 = pack2(wv.w, wv.w);
        const u64* ap = ap0 + ci * PSTR;
        const u64 a0 = ap[0], a1 = ap[1], a2 = ap[2], a3 = ap[3];
        ffma2(acc[0][0], a0, w0); ffma2(acc[0][1], a0, w1);
        ffma2(acc[0][2], a0, w2); ffma2(acc[0][3], a0, w3);
        ffma2(acc[1][0], a1, w0); ffma2(acc[1][1], a1, w1);
        ffma2(acc[1][2], a1, w2); ffma2(acc[1][3], a1, w3);
        ffma2(acc[2][0], a2, w0); ffma2(acc[2][1], a2, w1);
        ffma2(acc[2][2], a2, w2); ffma2(acc[2][3], a2, w3);
        ffma2(acc[3][0], a3, w0); ffma2(acc[3][1], a3, w1);
        ffma2(acc[3][2], a3, w2); ffma2(acc[3][3], a3, w3);
    }
    const float4 bv = *(const float4*)(bias + boff + tx * 4);
    #pragma unroll
    for (int p = 0; p < 4; ++p) {
        float l0, h0, l1, h1, l2, h2, l3, h3;
        unpack2(acc[p][0], l0, h0); unpack2(acc[p][1], l1, h1);
        unpack2(acc[p][2], l2, h2); unpack2(acc[p][3], l3, h3);
        float4 f0, f1;
        f0.x = l0 + bv.x; f0.y = l1 + bv.y; f0.z = l2 + bv.z; f0.w = l3 + bv.w;
        f1.x = h0 + bv.x; f1.y = h1 + bv.y; f1.z = h2 + bv.z; f1.w = h3 + bv.w;
        *(float4*)(out_s + (g * 8 + 2 * p)     * STR + tx * 4) = f0;
        *(float4*)(out_s + (g * 8 + 2 * p + 1) * STR + tx * 4) = f1;
    }
}

// ---------------- kernel 2 ----------------
__global__ __launch_bounds__(NTHR)
void k_main(const float* __restrict__ rpp,
            const float* __restrict__ q_w,  const float* __restrict__ q_b,
            const float* __restrict__ kv_w, const float* __restrict__ kv_b,
            const float* __restrict__ o_w,  const float* __restrict__ o_b,
            float* __restrict__ out)
{
    extern __shared__ float sm[];
    // four 8448-float buffers (33792 B each)
    float* bufP1f = sm;                    // xwP (u64 view) -> k [tok][ch]
    float* bufP2f = bufP1f + CH * PSTR * 2;// xd2P -> attnP (u64 views)
    float* buf3   = bufP2f + CH * PSTR * 2;// xd [tok][ch] -> q [tok][ch]
    float* buf4   = buf3 + P2 * STR;       // v [tok][ch]
    float* sSim   = buf4 + P2 * STR;       // 64x64
    float* sW     = sSim + 4096;
    int*   sIdx   = (int*)(sW + 256);

    u64* xwP  = (u64*)bufP1f;
    u64* xd2P = (u64*)bufP2f;
    u64* attP = (u64*)bufP2f;

    const int win = blockIdx.x;
    const int b   = win >> 10;
    const int wr  = win & 1023;
    const int wi  = wr >> 5;
    const int wj  = wr & 31;
    const int tid = threadIdx.x;
    const int wp  = tid >> 5, tx = tid & 31;

    // ---- inter-window bilinear blend -> buf3 (xd, [tok][ch]) ----
    {
        const float ox = g_oi[win * 2 + 0], oy = g_oi[win * 2 + 1];
        const float gxp = (float)wj + ox, gyp = (float)wi + oy;
        const float x0f = floorf(gxp), y0f = floorf(gyp);
        const float fx = gxp - x0f, fy = gyp - y0f;
        const int x0 = (int)x0f, y0 = (int)y0f;
        const float wgt[4] = {(1.f - fx) * (1.f - fy), fx * (1.f - fy),
                              (1.f - fx) * fy,          fx * fy};
        const float4* nb[4];
        float nww[4];
        #pragma unroll
        for (int k = 0; k < 4; ++k) {
            const int xx = x0 + (k & 1), yy = y0 + (k >> 1);
            const bool valid = (xx >= 0) && (xx < W1G) && (yy >= 0) && (yy < W1G);
            nb[k]  = (const float4*)(valid ? (g_xw + (size_t)((b << 10) + (yy << 5) + xx) * P2 * CH)
                                           : g_xw);
            nww[k] = valid ? wgt[k] : 0.f;
        }
        for (int i4 = tid; i4 < P2 * CH / 4; i4 += NTHR) {
            const float4 v0 = __ldg(nb[0] + i4), v1 = __ldg(nb[1] + i4);
            const float4 v2 = __ldg(nb[2] + i4), v3 = __ldg(nb[3] + i4);
            float4 r;
            r.x = nww[0]*v0.x + nww[1]*v1.x + nww[2]*v2.x + nww[3]*v3.x;
            r.y = nww[0]*v0.y + nww[1]*v1.y + nww[2]*v2.y + nww[3]*v3.y;
            r.z = nww[0]*v0.z + nww[1]*v1.z + nww[2]*v2.z + nww[3]*v3.z;
            r.w = nww[0]*v0.w + nww[1]*v1.w + nww[2]*v2.w + nww[3]*v3.w;
            *(float4*)(buf3 + (i4 >> 5) * STR + (i4 & 31) * 4) = r;
        }
    }
    if (tid < 64) {
        const int tok = tid, pi = tok >> 3, pj = tok & 7;
        const float o0 = g_off[win * 128 + tok * 2], o1 = g_off[win * 128 + tok * 2 + 1];
        const float gx2 = (float)pj + o0, gy2 = (float)pi + o1;
        const float xf = floorf(gx2), yf = floorf(gy2);
        const float fx = gx2 - xf, fy = gy2 - yf;
        const int x0 = (int)xf, y0 = (int)yf;
        const float ww[4] = {(1.f - fx) * (1.f - fy), fx * (1.f - fy),
                             (1.f - fx) * fy,          fx * fy};
        #pragma unroll
        for (int k = 0; k < 4; ++k) {
            const int xx = x0 + (k & 1), yy = y0 + (k >> 1);
            const bool valid = (xx >= 0) && (xx < WSZ) && (yy >= 0) && (yy < WSZ);
            sIdx[tok * 4 + k] = valid ? (yy * 8 + xx) : 0;
            sW[tok * 4 + k]   = valid ? ww[k] : 0.f;
        }
    }
    __syncthreads();

    // ---- intra-window gather -> xd2P pairs; load g_xwT -> xwP ----
    {
        const u64* src = g_xwT + (size_t)win * CH * 32;
        #pragma unroll
        for (int it = 0; it < 8; ++it) {
            const int i  = tid + it * NTHR;      // 4096 (ch, pair) jobs
            const int pr = i & 31, ch = i >> 5;
            // xwP copy (coalesced gmem -> conflict-free STS.64)
            xwP[ch * PSTR + pr] = __ldg(src + ch * 32 + pr);
            // gather two tokens of this pair
            const int t0 = 2 * pr, t1 = 2 * pr + 1;
            float v0 = 0.f, v1 = 0.f;
            #pragma unroll
            for (int k = 0; k < 4; ++k) {
                v0 = fmaf(sW[t0 * 4 + k], buf3[sIdx[t0 * 4 + k] * STR + ch], v0);
                v1 = fmaf(sW[t1 * 4 + k], buf3[sIdx[t1 * 4 + k] * STR + ch], v1);
            }
            xd2P[ch * PSTR + pr] = pack2(v0, v1);
        }
    }
    __syncthreads();

    // ---- phase A: q (warps 0-7: xwP -> buf3)  ||  v (warps 8-15: xd2P -> buf4) ----
    if (wp < 8) gemm_p(xwP,  q_w, 128, 0,   q_b,  0,   buf3, wp,     tx);
    else        gemm_p(xd2P, kv_w, 256, 128, kv_b, 128, buf4, wp - 8, tx);
    __syncthreads();
    // ---- phase B: k (warps 0-7: xd2P -> bufP1f) ----
    if (wp < 8) gemm_p(xd2P, kv_w, 256, 0, kv_b, 0, bufP1f, wp, tx);
    __syncthreads();

    // ---- attention: each warp owns 4 query rows (r0 = wp*4) ----
    const float* sQ = buf3;
    const float* sK = bufP1f;
    const float* sV = buf4;
    const float scale = 0.17677669529663687f;
    const bool lastRow = (wi == W1G - 1), lastCol = (wj == W1G - 1);
    const int r0 = wp * 4;
    for (int hh = 0; hh < NH; ++hh) {
        float acc[4][2] = {};
        const float* qp   = sQ + r0 * STR + hh * HD;
        const float4* k0p = (const float4*)(sK + tx * STR + hh * HD);
        const float4* k1p = (const float4*)(sK + (tx + 32) * STR + hh * HD);
        #pragma unroll
        for (int d4 = 0; d4 < HD / 4; ++d4) {
            const float4 kk0 = k0p[d4], kk1 = k1p[d4];
            #pragma unroll
            for (int r = 0; r < 4; ++r) {
                const float4 qq = *(const float4*)(qp + r * STR + d4 * 4);
                acc[r][0] = fmaf(qq.x, kk0.x, acc[r][0]);
                acc[r][0] = fmaf(qq.y, kk0.y, acc[r][0]);
                acc[r][0] = fmaf(qq.z, kk0.z, acc[r][0]);
                acc[r][0] = fmaf(qq.w, kk0.w, acc[r][0]);
                acc[r][1] = fmaf(qq.x, kk1.x, acc[r][1]);
                acc[r][1] = fmaf(qq.y, kk1.y, acc[r][1]);
                acc[r][1] = fmaf(qq.z, kk1.z, acc[r][1]);
                acc[r][1] = fmaf(qq.w, kk1.w, acc[r][1]);
            }
        }
        const float* rb = rpp + hh * 225;
        #pragma unroll
        for (int r = 0; r < 4; ++r) {
            const int i = r0 + r, pi_i = i >> 3, pj_i = i & 7;
            #pragma unroll
            for (int u = 0; u < 2; ++u) {
                const int j = tx + 32 * u, pi_j = j >> 3, pj_j = j & 7;
                const float bias = rb[(pi_i - pi_j + 7) * 15 + (pj_i - pj_j + 7)];
                const bool msk = (lastRow && ((pi_i < 4) != (pi_j < 4)))
                              || (lastCol && ((pj_i < 4) != (pj_j < 4)));
                sSim[i * 64 + j] = msk ? -CUDART_INF_F : fmaf(acc[r][u], scale, bias);
            }
        }
        __syncwarp();
        #pragma unroll
        for (int r = 0; r < 4; ++r) {
            const int i = r0 + r;
            const float a = sSim[i * 64 + tx], bb = sSim[i * 64 + tx + 32];
            float m = fmaxf(a, bb);
            #pragma unroll
            for (int s2 = 16; s2 > 0; s2 >>= 1) m = fmaxf(m, __shfl_xor_sync(0xffffffffu, m, s2));
            const float e0 = __expf(a - m), e1 = __expf(bb - m);
            float s = e0 + e1;
            #pragma unroll
            for (int s2 = 16; s2 > 0; s2 >>= 1) s += __shfl_xor_sync(0xffffffffu, s, s2);
            const float inv = 1.f / s;
            sSim[i * 64 + tx]      = e0 * inv;
            sSim[i * 64 + tx + 32] = e1 * inv;
        }
        __syncwarp();
        float po[4] = {};
        #pragma unroll 4
        for (int j = 0; j < 64; ++j) {
            const float vv = sV[j * STR + hh * HD + tx];
            #pragma unroll
            for (int r = 0; r < 4; ++r)
                po[r] = fmaf(sSim[(r0 + r) * 64 + j], vv, po[r]);
        }
        // write attention output as pairs: attP[ch][pair], ch = hh*32+tx
        __syncwarp();
        const int ch = hh * HD + tx;
        attP[ch * PSTR + 2 * wp]     = pack2(po[0], po[1]);
        attP[ch * PSTR + 2 * wp + 1] = pack2(po[2], po[3]);
        __syncwarp();
    }
    __syncthreads();

    // ---- o projection from attP pairs (warps 0-7) + un-shift scatter ----
    if (wp < 8) {
        u64 acc[4][4] = {};
        const float* wbase = o_w + tx * 4;
        const u64*   ap0   = attP + 4 * wp;
        #pragma unroll 4
        for (int ci = 0; ci < 128; ++ci) {
            const float4 wv = __ldg((const float4*)(wbase + ci * 128));
            const u64 w0 = pack2(wv.x, wv.x), w1 = pack2(wv.y, wv.y);
            const u64 w2 = pack2(wv.z, wv.z), w3 = pack2(wv.w, wv.w);
            const u64* ap = ap0 + ci * PSTR;
            const u64 a0 = ap[0], a1 = ap[1], a2 = ap[2], a3 = ap[3];
            ffma2(acc[0][0], a0, w0); ffma2(acc[0][1], a0, w1);
            ffma2(acc[0][2], a0, w2); ffma2(acc[0][3], a0, w3);
            ffma2(acc[1][0], a1, w0); ffma2(acc[1][1], a1, w1);
            ffma2(acc[1][2], a1, w2); ffma2(acc[1][3], a1, w3);
            ffma2(acc[2][0], a2, w0); ffma2(acc[2][1], a2, w1);
            ffma2(acc[2][2], a2, w2); ffma2(acc[2][3], a2, w3);
            ffma2(acc[3][0], a3, w0); ffma2(acc[3][1], a3, w1);
            ffma2(acc[3][2], a3, w2); ffma2(acc[3][3], a3, w3);
        }
        const float4 bv = *(const float4*)(o_b + tx * 4);
        #pragma unroll
        for (int p = 0; p < 4; ++p) {
            float l0, h0, l1, h1, l2, h2, l3, h3;
            unpack2(acc[p][0], l0, h0); unpack2(acc[p][1], l1, h1);
            unpack2(acc[p][2], l2, h2); unpack2(acc[p][3], l3, h3);
            float4 f0, f1;
            f0.x = l0 + bv.x; f0.y = l1 + bv.y; f0.z = l2 + bv.z; f0.w = l3 + bv.w;
            f1.x = h0 + bv.x; f1.y = h1 + bv.y; f1.z = h2 + bv.z; f1.w = h3 + bv.w;
            const int t0 = wp * 8 + 2 * p;
            #pragma unroll
            for (int h = 0; h < 2; ++h) {
                const int tok = t0 + h, pi = tok >> 3, pj = tok & 7;
                const int rr = (wi * 8 + pi + SHIFT) & 255;
                const int cc = (wj * 8 + pj + SHIFT) & 255;
                *(float4*)(out + (size_t)((((b << 8) + rr) << 8) + cc) * CH + tx * 4)
                    = h ? f1 : f0;
            }
        }
    }
}

extern "C" void kernel_launch(void* const* d_in, const int* in_sizes, int n_in,
                              void* d_out, int out_size)
{
    const float* x    = (const float*)d_in[0];
    const float* rpp  = (const float*)d_in[1];
    const float* wi_w = (const float*)d_in[2];
    const float* wi_b = (const float*)d_in[3];
    const float* w1_w = (const float*)d_in[4];
    const float* w1_b = (const float*)d_in[5];
    const float* w2_w = (const float*)d_in[6];
    const float* w2_b = (const float*)d_in[7];
    const float* q_w  = (const float*)d_in[8];
    const float* q_b  = (const float*)d_in[9];
    const float* kv_w = (const float*)d_in[10];
    const float* kv_b = (const float*)d_in[11];
    const float* o_w  = (const float*)d_in[12];
    const float* o_b  = (const float*)d_in[13];
    float* out = (float*)d_out;

    // 4 x 8448 floats + sim + tables
    const size_t smem2 = (size_t)(4 * 8448 + 4096 + 256 + 256) * sizeof(float);
    cudaFuncSetAttribute(k_main, cudaFuncAttributeMaxDynamicSharedMemorySize, (int)smem2);

    k_prep<<<NWIN, 256>>>(x, wi_w, wi_b, w1_w, w1_b, w2_w, w2_b);
    k_main<<<NWIN, NTHR, smem2>>>(rpp, q_w, q_b, kv_w, kv_b, o_w, o_b, out);
}

// round 7
// speedup vs baseline: 1.2641x; 1.2641x over previous
#include <cuda_runtime.h>
#include <math_constants.h>

#define WSZ    8
#define P2     64
#define CH     128
#define W1G    32
#define NWPB   1024
#define BATCH  8
#define NWIN   (BATCH*NWPB)
#define HD     32
#define NH     4
#define SHIFT  4
#define PSTR   132         // k_prep scratch stride only
#define NTHR   512

// swizzled [64][128] buffers: float4 unit index for (tok, c4)
__device__ __forceinline__ int swz4(int tok, int c4) { return tok * 32 + (c4 ^ (tok & 7)); }
// scalar word index for (tok, ch)
__device__ __forceinline__ int swz(int tok, int ch) {
    return tok * 128 + ((((ch >> 2) ^ (tok & 7))) << 2) + (ch & 3);
}

// ---------------- scratch ----------------
__device__ float g_xw [(size_t)NWIN * P2 * CH];   // [win][tok][ch]
__device__ float g_off[NWIN * P2 * 2];
__device__ float g_oi [NWIN * 2];

// ---------------- kernel 1: window gather + offset MLPs ----------------
__global__ __launch_bounds__(256)
void k_prep(const float* __restrict__ x,
            const float* __restrict__ wi_w, const float* __restrict__ wi_b,
            const float* __restrict__ w1_w, const float* __restrict__ w1_b,
            const float* __restrict__ w2_w, const float* __restrict__ w2_b)
{
    __shared__ float sT[P2 * PSTR];
    __shared__ float sT1[P2 * 2];

    const int win = blockIdx.x;
    const int b   = win >> 10;
    const int wr  = win & 1023;
    const int wi  = wr >> 5;
    const int wj  = wr & 31;
    const int tid = threadIdx.x;

    float4* gx4 = (float4*)(g_xw + (size_t)win * P2 * CH);

    for (int i4 = tid; i4 < P2 * CH / 4; i4 += 256) {
        const int tok = i4 >> 5, c4 = i4 & 31;
        const int pi = tok >> 3, pj = tok & 7;
        const int r = (wi * 8 + pi + SHIFT) & 255;
        const int c = (wj * 8 + pj + SHIFT) & 255;
        const float4 v = *(const float4*)(x + (size_t)((((b << 8) + r) << 8) + c) * CH + c4 * 4);
        *(float4*)(sT + tok * PSTR + c4 * 4) = v;
        gx4[i4] = v;
    }
    __syncthreads();

    {
        const int kind = tid >> 7;
        const int rem  = tid & 127;
        const int tok  = rem >> 1;
        const int d    = rem & 1;
        const float* w = kind ? w1_w : wi_w;
        float acc = 0.f;
        #pragma unroll 8
        for (int ch = 0; ch < 128; ++ch)
            acc = fmaf(sT[tok * PSTR + ch], w[ch * 2 + d], acc);
        if (kind) sT1[tok * 2 + d] = acc + w1_b[d];
        else      g_off[win * 128 + tok * 2 + d] = acc + wi_b[d];
    }
    __syncthreads();

    if (tid < 2) {
        float acc = w2_b[tid];
        for (int f = 0; f < 128; ++f)
            acc = fmaf(sT1[f], w2_w[f * 2 + tid], acc);
        g_oi[win * 2 + tid] = acc;
    }
}

// 64x128 GEMM, 16 warps x 4 rows, A from swizzled smem.
__device__ __forceinline__
void gemm16_s(const float* __restrict__ in_s, const float* __restrict__ w,
              int wstride, int woff, const float* __restrict__ bias, int boff,
              float* __restrict__ out_s, int wp, int tx)
{
    float acc[4][4] = {};
    const int r0 = wp * 4;
    const float* wbase = w + woff + tx * 4;
    const float4* inv4 = (const float4*)in_s;
    #pragma unroll 4
    for (int c4 = 0; c4 < 32; ++c4) {
        const int ci = c4 * 4;
        const float4 w0 = __ldg((const float4*)(wbase + (size_t)(ci + 0) * wstride));
        const float4 w1 = __ldg((const float4*)(wbase + (size_t)(ci + 1) * wstride));
        const float4 w2 = __ldg((const float4*)(wbase + (size_t)(ci + 2) * wstride));
        const float4 w3 = __ldg((const float4*)(wbase + (size_t)(ci + 3) * wstride));
        #pragma unroll
        for (int r = 0; r < 4; ++r) {
            const float4 a = inv4[swz4(r0 + r, c4)];
            acc[r][0] = fmaf(a.x, w0.x, acc[r][0]);
            acc[r][1] = fmaf(a.x, w0.y, acc[r][1]);
            acc[r][2] = fmaf(a.x, w0.z, acc[r][2]);
            acc[r][3] = fmaf(a.x, w0.w, acc[r][3]);
            acc[r][0] = fmaf(a.y, w1.x, acc[r][0]);
            acc[r][1] = fmaf(a.y, w1.y, acc[r][1]);
            acc[r][2] = fmaf(a.y, w1.z, acc[r][2]);
            acc[r][3] = fmaf(a.y, w1.w, acc[r][3]);
            acc[r][0] = fmaf(a.z, w2.x, acc[r][0]);
            acc[r][1] = fmaf(a.z, w2.y, acc[r][1]);
            acc[r][2] = fmaf(a.z, w2.z, acc[r][2]);
            acc[r][3] = fmaf(a.z, w2.w, acc[r][3]);
            acc[r][0] = fmaf(a.w, w3.x, acc[r][0]);
            acc[r][1] = fmaf(a.w, w3.y, acc[r][1]);
            acc[r][2] = fmaf(a.w, w3.z, acc[r][2]);
            acc[r][3] = fmaf(a.w, w3.w, acc[r][3]);
        }
    }
    const float4 bv = *(const float4*)(bias + boff + tx * 4);
    float4* outv4 = (float4*)out_s;
    #pragma unroll
    for (int r = 0; r < 4; ++r) {
        float4 o;
        o.x = acc[r][0] + bv.x; o.y = acc[r][1] + bv.y;
        o.z = acc[r][2] + bv.z; o.w = acc[r][3] + bv.w;
        outv4[swz4(r0 + r, tx)] = o;
    }
}

// same but A streamed from gmem ([tok][ch] linear, broadcast __ldg)
__device__ __forceinline__
void gemm16_g(const float* __restrict__ in_g, const float* __restrict__ w,
              int wstride, int woff, const float* __restrict__ bias, int boff,
              float* __restrict__ out_s, int wp, int tx)
{
    float acc[4][4] = {};
    const int r0 = wp * 4;
    const float* wbase = w + woff + tx * 4;
    #pragma unroll 4
    for (int c4 = 0; c4 < 32; ++c4) {
        const int ci = c4 * 4;
        const float4 w0 = __ldg((const float4*)(wbase + (size_t)(ci + 0) * wstride));
        const float4 w1 = __ldg((const float4*)(wbase + (size_t)(ci + 1) * wstride));
        const float4 w2 = __ldg((const float4*)(wbase + (size_t)(ci + 2) * wstride));
        const float4 w3 = __ldg((const float4*)(wbase + (size_t)(ci + 3) * wstride));
        #pragma unroll
        for (int r = 0; r < 4; ++r) {
            const float4 a = __ldg((const float4*)(in_g + (r0 + r) * CH + ci));
            acc[r][0] = fmaf(a.x, w0.x, acc[r][0]);
            acc[r][1] = fmaf(a.x, w0.y, acc[r][1]);
            acc[r][2] = fmaf(a.x, w0.z, acc[r][2]);
            acc[r][3] = fmaf(a.x, w0.w, acc[r][3]);
            acc[r][0] = fmaf(a.y, w1.x, acc[r][0]);
            acc[r][1] = fmaf(a.y, w1.y, acc[r][1]);
            acc[r][2] = fmaf(a.y, w1.z, acc[r][2]);
            acc[r][3] = fmaf(a.y, w1.w, acc[r][3]);
            acc[r][0] = fmaf(a.z, w2.x, acc[r][0]);
            acc[r][1] = fmaf(a.z, w2.y, acc[r][1]);
            acc[r][2] = fmaf(a.z, w2.z, acc[r][2]);
            acc[r][3] = fmaf(a.z, w2.w, acc[r][3]);
            acc[r][0] = fmaf(a.w, w3.x, acc[r][0]);
            acc[r][1] = fmaf(a.w, w3.y, acc[r][1]);
            acc[r][2] = fmaf(a.w, w3.z, acc[r][2]);
            acc[r][3] = fmaf(a.w, w3.w, acc[r][3]);
        }
    }
    const float4 bv = *(const float4*)(bias + boff + tx * 4);
    float4* outv4 = (float4*)out_s;
    #pragma unroll
    for (int r = 0; r < 4; ++r) {
        float4 o;
        o.x = acc[r][0] + bv.x; o.y = acc[r][1] + bv.y;
        o.z = acc[r][2] + bv.z; o.w = acc[r][3] + bv.w;
        outv4[swz4(r0 + r, tx)] = o;
    }
}

// ---------------- kernel 2 ----------------
__global__ __launch_bounds__(NTHR, 2)
void k_main(const float* __restrict__ rpp,
            const float* __restrict__ q_w,  const float* __restrict__ q_b,
            const float* __restrict__ kv_w, const float* __restrict__ kv_b,
            const float* __restrict__ o_w,  const float* __restrict__ o_b,
            float* __restrict__ out)
{
    extern __shared__ float sm[];
    float* bufA = sm;            // q -> attn-out
    float* bufB = bufA + 8192;   // xd2 -> k (in-place)
    float* bufC = bufB + 8192;   // xd -> v
    float* sSim = bufC + 8192;   // 64x64

    const int win = blockIdx.x;
    const int b   = win >> 10;
    const int wr  = win & 1023;
    const int wi  = wr >> 5;
    const int wj  = wr & 31;
    const int tid = threadIdx.x;
    const int wp  = tid >> 5, tx = tid & 31;

    // ---- inter-window bilinear blend -> bufC (xd) ----
    {
        const float ox = __ldg(g_oi + win * 2 + 0), oy = __ldg(g_oi + win * 2 + 1);
        const float gxp = (float)wj + ox, gyp = (float)wi + oy;
        const float x0f = floorf(gxp), y0f = floorf(gyp);
        const float fx = gxp - x0f, fy = gyp - y0f;
        const int x0 = (int)x0f, y0 = (int)y0f;
        const float wgt[4] = {(1.f - fx) * (1.f - fy), fx * (1.f - fy),
                              (1.f - fx) * fy,          fx * fy};
        const float4* nb[4];
        float nww[4];
        #pragma unroll
        for (int k = 0; k < 4; ++k) {
            const int xx = x0 + (k & 1), yy = y0 + (k >> 1);
            const bool valid = (xx >= 0) && (xx < W1G) && (yy >= 0) && (yy < W1G);
            nb[k]  = (const float4*)(valid ? (g_xw + (size_t)((b << 10) + (yy << 5) + xx) * P2 * CH)
                                           : g_xw);
            nww[k] = valid ? wgt[k] : 0.f;
        }
        float4* outv4 = (float4*)bufC;
        for (int i4 = tid; i4 < 2048; i4 += NTHR) {
            const float4 v0 = __ldg(nb[0] + i4), v1 = __ldg(nb[1] + i4);
            const float4 v2 = __ldg(nb[2] + i4), v3 = __ldg(nb[3] + i4);
            float4 r;
            r.x = nww[0]*v0.x + nww[1]*v1.x + nww[2]*v2.x + nww[3]*v3.x;
            r.y = nww[0]*v0.y + nww[1]*v1.y + nww[2]*v2.y + nww[3]*v3.y;
            r.z = nww[0]*v0.z + nww[1]*v1.z + nww[2]*v2.z + nww[3]*v3.z;
            r.w = nww[0]*v0.w + nww[1]*v1.w + nww[2]*v2.w + nww[3]*v3.w;
            outv4[swz4(i4 >> 5, i4 & 31)] = r;
        }
    }
    __syncthreads();

    // ---- intra-window gather bufC -> bufB (xd2); offsets recomputed ----
    {
        const float4* inv4 = (const float4*)bufC;
        float4* outv4 = (float4*)bufB;
        #pragma unroll
        for (int it = 0; it < 4; ++it) {
            const int i4 = tid + it * NTHR;
            const int tok = i4 >> 5, c4 = i4 & 31;
            const int pi = tok >> 3, pj = tok & 7;
            const float o0 = __ldg(g_off + win * 128 + tok * 2);
            const float o1 = __ldg(g_off + win * 128 + tok * 2 + 1);
            const float gx2 = (float)pj + o0, gy2 = (float)pi + o1;
            const float xf = floorf(gx2), yf = floorf(gy2);
            const float fx = gx2 - xf, fy = gy2 - yf;
            const int x0 = (int)xf, y0 = (int)yf;
            const float ww[4] = {(1.f - fx) * (1.f - fy), fx * (1.f - fy),
                                 (1.f - fx) * fy,          fx * fy};
            float4 r = make_float4(0.f, 0.f, 0.f, 0.f);
            #pragma unroll
            for (int k = 0; k < 4; ++k) {
                const int xx = x0 + (k & 1), yy = y0 + (k >> 1);
                const bool valid = (xx >= 0) && (xx < WSZ) && (yy >= 0) && (yy < WSZ);
                const int idx = valid ? (yy * 8 + xx) : 0;
                const float wk = valid ? ww[k] : 0.f;
                const float4 a = inv4[swz4(idx, c4)];
                r.x = fmaf(wk, a.x, r.x);
                r.y = fmaf(wk, a.y, r.y);
                r.z = fmaf(wk, a.z, r.z);
                r.w = fmaf(wk, a.w, r.w);
            }
            outv4[swz4(tok, c4)] = r;
        }
    }
    __syncthreads();

    // ---- GEMMs, all 16 warps each ----
    // q: A = xw from gmem -> bufA
    gemm16_g(g_xw + (size_t)win * P2 * CH, q_w, 128, 0, q_b, 0, bufA, wp, tx);
    // v: A = xd2 (bufB) -> bufC (xd dead)
    gemm16_s(bufB, kv_w, 256, 128, kv_b, 128, bufC, wp, tx);
    // k: A = xd2 (bufB) -> bufB in-place (warp-local rows)
    gemm16_s(bufB, kv_w, 256, 0, kv_b, 0, bufB, wp, tx);
    __syncthreads();

    // ---- attention: each warp owns 4 query rows ----
    const float scale = 0.17677669529663687f;
    const bool lastRow = (wi == W1G - 1), lastCol = (wj == W1G - 1);
    const int r0 = wp * 4;
    const float4* qv4 = (const float4*)bufA;
    const float4* kv4 = (const float4*)bufB;
    for (int hh = 0; hh < NH; ++hh) {
        float acc[4][2] = {};
        #pragma unroll
        for (int d4 = 0; d4 < HD / 4; ++d4) {
            const float4 kk0 = kv4[swz4(tx,      hh * 8 + d4)];
            const float4 kk1 = kv4[swz4(tx + 32, hh * 8 + d4)];
            #pragma unroll
            for (int r = 0; r < 4; ++r) {
                const float4 qq = qv4[swz4(r0 + r, hh * 8 + d4)];
                acc[r][0] = fmaf(qq.x, kk0.x, acc[r][0]);
                acc[r][0] = fmaf(qq.y, kk0.y, acc[r][0]);
                acc[r][0] = fmaf(qq.z, kk0.z, acc[r][0]);
                acc[r][0] = fmaf(qq.w, kk0.w, acc[r][0]);
                acc[r][1] = fmaf(qq.x, kk1.x, acc[r][1]);
                acc[r][1] = fmaf(qq.y, kk1.y, acc[r][1]);
                acc[r][1] = fmaf(qq.z, kk1.z, acc[r][1]);
                acc[r][1] = fmaf(qq.w, kk1.w, acc[r][1]);
            }
        }
        const float* rb = rpp + hh * 225;
        #pragma unroll
        for (int r = 0; r < 4; ++r) {
            const int i = r0 + r, pi_i = i >> 3, pj_i = i & 7;
            #pragma unroll
            for (int u = 0; u < 2; ++u) {
                const int j = tx + 32 * u, pi_j = j >> 3, pj_j = j & 7;
                const float bias = rb[(pi_i - pi_j + 7) * 15 + (pj_i - pj_j + 7)];
                const bool msk = (lastRow && ((pi_i < 4) != (pi_j < 4)))
                              || (lastCol && ((pj_i < 4) != (pj_j < 4)));
                sSim[i * 64 + j] = msk ? -CUDART_INF_F : fmaf(acc[r][u], scale, bias);
            }
        }
        __syncwarp();
        #pragma unroll
        for (int r = 0; r < 4; ++r) {
            const int i = r0 + r;
            const float a = sSim[i * 64 + tx], bb = sSim[i * 64 + tx + 32];
            float m = fmaxf(a, bb);
            #pragma unroll
            for (int s2 = 16; s2 > 0; s2 >>= 1) m = fmaxf(m, __shfl_xor_sync(0xffffffffu, m, s2));
            const float e0 = __expf(a - m), e1 = __expf(bb - m);
            float s = e0 + e1;
            #pragma unroll
            for (int s2 = 16; s2 > 0; s2 >>= 1) s += __shfl_xor_sync(0xffffffffu, s, s2);
            const float inv = 1.f / s;
            sSim[i * 64 + tx]      = e0 * inv;
            sSim[i * 64 + tx + 32] = e1 * inv;
        }
        __syncwarp();
        float po[4] = {};
        #pragma unroll 4
        for (int j = 0; j < 64; ++j) {
            const float vv = bufC[swz(j, hh * HD + tx)];
            #pragma unroll
            for (int r = 0; r < 4; ++r)
                po[r] = fmaf(sSim[(r0 + r) * 64 + j], vv, po[r]);
        }
        __syncwarp();
        #pragma unroll
        for (int r = 0; r < 4; ++r)
            bufA[swz(r0 + r, hh * HD + tx)] = po[r];
        __syncwarp();
    }

    // ---- o projection (16 warps x 4 rows, warp-local rows of bufA) ----
    {
        float acc[4][4] = {};
        const float* wbase = o_w + tx * 4;
        const float4* inv4 = (const float4*)bufA;
        #pragma unroll 4
        for (int c4 = 0; c4 < 32; ++c4) {
            const int ci = c4 * 4;
            const float4 w0 = __ldg((const float4*)(wbase + (ci + 0) * 128));
            const float4 w1 = __ldg((const float4*)(wbase + (ci + 1) * 128));
            const float4 w2 = __ldg((const float4*)(wbase + (ci + 2) * 128));
            const float4 w3 = __ldg((const float4*)(wbase + (ci + 3) * 128));
            #pragma unroll
            for (int r = 0; r < 4; ++r) {
                const float4 a = inv4[swz4(r0 + r, c4)];
                acc[r][0] = fmaf(a.x, w0.x, acc[r][0]);
                acc[r][1] = fmaf(a.x, w0.y, acc[r][1]);
                acc[r][2] = fmaf(a.x, w0.z, acc[r][2]);
                acc[r][3] = fmaf(a.x, w0.w, acc[r][3]);
                acc[r][0] = fmaf(a.y, w1.x, acc[r][0]);
                acc[r][1] = fmaf(a.y, w1.y, acc[r][1]);
                acc[r][2] = fmaf(a.y, w1.z, acc[r][2]);
                acc[r][3] = fmaf(a.y, w1.w, acc[r][3]);
                acc[r][0] = fmaf(a.z, w2.x, acc[r][0]);
                acc[r][1] = fmaf(a.z, w2.y, acc[r][1]);
                acc[r][2] = fmaf(a.z, w2.z, acc[r][2]);
                acc[r][3] = fmaf(a.z, w2.w, acc[r][3]);
                acc[r][0] = fmaf(a.w, w3.x, acc[r][0]);
                acc[r][1] = fmaf(a.w, w3.y, acc[r][1]);
                acc[r][2] = fmaf(a.w, w3.z, acc[r][2]);
                acc[r][3] = fmaf(a.w, w3.w, acc[r][3]);
            }
        }
        const float4 bv = *(const float4*)(o_b + tx * 4);
        #pragma unroll
        for (int r = 0; r < 4; ++r) {
            const int tok = r0 + r, pi = tok >> 3, pj = tok & 7;
            const int rr = (wi * 8 + pi + SHIFT) & 255;
            const int cc = (wj * 8 + pj + SHIFT) & 255;
            float4 o;
            o.x = acc[r][0] + bv.x; o.y = acc[r][1] + bv.y;
            o.z = acc[r][2] + bv.z; o.w = acc[r][3] + bv.w;
            *(float4*)(out + (size_t)((((b << 8) + rr) << 8) + cc) * CH + tx * 4) = o;
        }
    }
}

extern "C" void kernel_launch(void* const* d_in, const int* in_sizes, int n_in,
                              void* d_out, int out_size)
{
    const float* x    = (const float*)d_in[0];
    const float* rpp  = (const float*)d_in[1];
    const float* wi_w = (const float*)d_in[2];
    const float* wi_b = (const float*)d_in[3];
    const float* w1_w = (const float*)d_in[4];
    const float* w1_b = (const float*)d_in[5];
    const float* w2_w = (const float*)d_in[6];
    const float* w2_b = (const float*)d_in[7];
    const float* q_w  = (const float*)d_in[8];
    const float* q_b  = (const float*)d_in[9];
    const float* kv_w = (const float*)d_in[10];
    const float* kv_b = (const float*)d_in[11];
    const float* o_w  = (const float*)d_in[12];
    const float* o_b  = (const float*)d_in[13];
    float* out = (float*)d_out;

    // 3*8192 + 4096 floats = 114688 bytes = 112 KB -> 2 CTAs/SM
    const size_t smem2 = (size_t)(3 * 8192 + 4096) * sizeof(float);
    cudaFuncSetAttribute(k_main, cudaFuncAttributeMaxDynamicSharedMemorySize, (int)smem2);

    k_prep<<<NWIN, 256>>>(x, wi_w, wi_b, w1_w, w1_b, w2_w, w2_b);
    k_main<<<NWIN, NTHR, smem2>>>(rpp, q_w, q_b, kv_w, kv_b, o_w, o_b, out);
}